// round 13
// baseline (speedup 1.0000x reference)
#include <cuda_runtime.h>
#include <cuda_fp16.h>
#include <cuda_bf16.h>
#include <math.h>

// Problem constants
#define B_  2
#define T_  2048
#define C_  1024
#define H_  16
#define D_  64
#define M_  (B_ * T_)          // 4096
#define N_  C_                 // 1024
#define K_  C_                 // 1024

// ---------------------------------------------------------------------------
// Scratch (no cudaMalloc allowed)
// ---------------------------------------------------------------------------
__device__ __half g_xh[M_ * K_];                 // x in fp16
__device__ __half g_wh[4][N_ * K_];              // wq, wk, wv, wo in fp16
__device__ __half g_qh[B_ * H_ * T_ * D_];       // Q (roped, scaled by log2e/8)
__device__ __half g_kh[B_ * H_ * T_ * D_];       // K (roped)  [b,h,t,d]
__device__ __half g_vh[B_ * H_ * D_ * T_];       // V^T        [b,h,d,t]
__device__ __half g_ah[M_ * C_];                 // attn out   [b*t, h*d]
__device__ float  g_cos[T_ * D_];
__device__ float  g_sin[T_ * D_];

// ---------------------------------------------------------------------------
// Helpers
// ---------------------------------------------------------------------------
__device__ __forceinline__ void mma16816(float* c, const unsigned* a,
                                         unsigned b0, unsigned b1) {
    asm volatile(
        "mma.sync.aligned.m16n8k16.row.col.f32.f16.f16.f32 "
        "{%0,%1,%2,%3},{%4,%5,%6,%7},{%8,%9},{%0,%1,%2,%3};\n"
        : "+f"(c[0]), "+f"(c[1]), "+f"(c[2]), "+f"(c[3])
        : "r"(a[0]), "r"(a[1]), "r"(a[2]), "r"(a[3]), "r"(b0), "r"(b1));
}

// fp16-accumulate variant (C/D are 2 b32 regs = 4 halfs)
__device__ __forceinline__ void mma16816h(unsigned* c, const unsigned* a,
                                          unsigned b0, unsigned b1) {
    asm volatile(
        "mma.sync.aligned.m16n8k16.row.col.f16.f16.f16.f16 "
        "{%0,%1},{%2,%3,%4,%5},{%6,%7},{%0,%1};\n"
        : "+r"(c[0]), "+r"(c[1])
        : "r"(a[0]), "r"(a[1]), "r"(a[2]), "r"(a[3]), "r"(b0), "r"(b1));
}

__device__ __forceinline__ unsigned ph2(float lo, float hi) {
    __half2 h = __floats2half2_rn(lo, hi);
    return *reinterpret_cast<unsigned*>(&h);
}

__device__ __forceinline__ float ex2(float x) {
    float r;
    asm("ex2.approx.f32 %0, %1;" : "=f"(r) : "f"(x));
    return r;
}

__device__ __forceinline__ float2 h22f2(unsigned u) {
    __half2 h = *reinterpret_cast<__half2*>(&u);
    return __half22float2(h);
}

__device__ __forceinline__ unsigned sptr(const void* p) {
    return (unsigned)__cvta_generic_to_shared(p);
}

__device__ __forceinline__ void ldm_x4(unsigned& r0, unsigned& r1,
                                       unsigned& r2, unsigned& r3,
                                       const __half* p) {
    asm volatile("ldmatrix.sync.aligned.m8n8.x4.shared.b16 {%0,%1,%2,%3}, [%4];\n"
                 : "=r"(r0), "=r"(r1), "=r"(r2), "=r"(r3) : "r"(sptr(p)));
}

__device__ __forceinline__ void cp16(void* s, const void* g) {
    asm volatile("cp.async.cg.shared.global [%0], [%1], 16;\n"
                 :: "r"(sptr(s)), "l"(g));
}
#define CP_COMMIT() asm volatile("cp.async.commit_group;\n")
#define CP_WAIT1()  asm volatile("cp.async.wait_group 1;\n")
#define CP_WAIT0()  asm volatile("cp.async.wait_group 0;\n")

// 0.125 (1/sqrt(D)) * log2(e): folded into Q so softmax uses bare EX2
#define QSCALE 0.18033688011112042f

// ---------------------------------------------------------------------------
// RoPE tables
// ---------------------------------------------------------------------------
__global__ void rope_tables_kernel() {
    int t = blockIdx.x;
    int d = threadIdx.x;           // 0..63
    float ex   = (float)(2 * (d & 31)) / 64.0f;
    float invf = powf(10000.0f, -ex);
    float ang  = (float)t * invf;
    g_cos[t * D_ + d] = cosf(ang);
    g_sin[t * D_ + d] = sinf(ang);
}

// ---------------------------------------------------------------------------
// Fused fp32 -> fp16 convert of x + all four weights (single launch)
// ---------------------------------------------------------------------------
__global__ void convert_all_kernel(const float4* __restrict__ x,
                                   const float4* __restrict__ wq,
                                   const float4* __restrict__ wk,
                                   const float4* __restrict__ wv,
                                   const float4* __restrict__ wo) {
    const int NX = M_ * K_ / 4;    // 1048576
    const int NW = N_ * K_ / 4;    // 262144
    int i = blockIdx.x * blockDim.x + threadIdx.x;
    const float4* s; uint2* d; int j;
    if (i < NX) {
        s = x; d = (uint2*)g_xh; j = i;
    } else {
        int k = i - NX;
        int w = k / NW;            // 0..3
        j = k - w * NW;
        s = (w == 0) ? wq : (w == 1) ? wk : (w == 2) ? wv : wo;
        d = (uint2*)g_wh[w];
    }
    float4 v = s[j];
    __half2 a = __floats2half2_rn(v.x, v.y);
    __half2 b = __floats2half2_rn(v.z, v.w);
    d[j] = make_uint2(*reinterpret_cast<unsigned*>(&a),
                      *reinterpret_cast<unsigned*>(&b));
}

// ---------------------------------------------------------------------------
// GEMM v2:  out[m,n] = sum_k A[m,k] * W[n,k] + bias[n]
// Block tile 128x128, 4 warps, warp tile 64x64 (LDSM:MMA = 8:32 = 0.25,
// vs 0.375 before — gemm was L1-bound at 54.8%).  Double-buffered cp.async.
// MODE 0 epilogue: bias + RoPE; q additionally scaled by QSCALE.
// ---------------------------------------------------------------------------
template <int MODE>
__global__ __launch_bounds__(128)
void gemm_kernel(const __half* __restrict__ A,
                 const float* __restrict__ biasq,
                 const float* __restrict__ biask,
                 const float* __restrict__ biasv,
                 const float* __restrict__ biaso,
                 float* __restrict__ out) {
    extern __shared__ __half sm[];
    __half (*As)[128][72] = (__half(*)[128][72])sm;
    __half (*Bs)[128][72] = (__half(*)[128][72])(sm + 2 * 128 * 72);

    const int n0 = blockIdx.x * 128;
    const int m0 = blockIdx.y * 128;
    const int z  = (MODE == 0) ? blockIdx.z : 3;
    const __half* __restrict__ W = g_wh[z];

    const int tid  = threadIdx.x;
    const int wid  = tid >> 5;     // 0..3
    const int lane = tid & 31;
    const int wm   = wid >> 1;     // 0..1  (m block of 64)
    const int wn   = wid & 1;      // 0..1  (n block of 64)
    const int g    = lane >> 2;
    const int tq   = lane & 3;

    const int la_row = (lane & 7) + (((lane >> 3) & 1) << 3);
    const int la_col = (lane >> 4) << 3;
    const int lb_row = (lane & 7) + ((lane >> 4) << 3);
    const int lb_col = ((lane >> 3) & 1) << 3;

    float acc[4][8][4];
#pragma unroll
    for (int mi = 0; mi < 4; mi++)
#pragma unroll
        for (int ni = 0; ni < 8; ni++)
#pragma unroll
            for (int j = 0; j < 4; j++) acc[mi][ni][j] = 0.0f;

    const int NT = K_ / 64;

    {
#pragma unroll
        for (int i = 0; i < 8; i++) {
            int idx = tid + i * 128;           // 0..1023
            int r = idx >> 3, c = (idx & 7) * 8;
            cp16(&As[0][r][c], &A[(size_t)(m0 + r) * K_ + c]);
            cp16(&Bs[0][r][c], &W[(size_t)(n0 + r) * K_ + c]);
        }
        CP_COMMIT();
    }

    for (int kt = 0; kt < NT; kt++) {
        int st = kt & 1;
        if (kt + 1 < NT) {
            int sn = st ^ 1;
#pragma unroll
            for (int i = 0; i < 8; i++) {
                int idx = tid + i * 128;
                int r = idx >> 3, c = (idx & 7) * 8;
                cp16(&As[sn][r][c], &A[(size_t)(m0 + r) * K_ + (kt + 1) * 64 + c]);
                cp16(&Bs[sn][r][c], &W[(size_t)(n0 + r) * K_ + (kt + 1) * 64 + c]);
            }
            CP_COMMIT();
            CP_WAIT1();
        } else {
            CP_WAIT0();
        }
        __syncthreads();

#pragma unroll
        for (int ks = 0; ks < 4; ks++) {
            unsigned a[4][4];
#pragma unroll
            for (int mi = 0; mi < 4; mi++) {
                ldm_x4(a[mi][0], a[mi][1], a[mi][2], a[mi][3],
                       &As[st][wm * 64 + mi * 16 + la_row][ks * 16 + la_col]);
            }
            unsigned bf[4][4];
#pragma unroll
            for (int ni2 = 0; ni2 < 4; ni2++) {
                ldm_x4(bf[ni2][0], bf[ni2][1], bf[ni2][2], bf[ni2][3],
                       &Bs[st][wn * 64 + ni2 * 16 + lb_row][ks * 16 + lb_col]);
            }
#pragma unroll
            for (int mi = 0; mi < 4; mi++)
#pragma unroll
                for (int ni = 0; ni < 8; ni++) {
                    unsigned b0 = bf[ni >> 1][(ni & 1) * 2];
                    unsigned b1 = bf[ni >> 1][(ni & 1) * 2 + 1];
                    mma16816(acc[mi][ni], a[mi], b0, b1);
                }
        }
        __syncthreads();
    }

    const float* bias = (MODE == 1) ? biaso : (z == 0 ? biasq : (z == 1 ? biask : biasv));

#pragma unroll
    for (int mi = 0; mi < 4; mi++) {
#pragma unroll
        for (int rsel = 0; rsel < 2; rsel++) {
            int m = m0 + wm * 64 + mi * 16 + g + rsel * 8;
            int t = m & (T_ - 1);
            int b = m >> 11;
#pragma unroll
            for (int ni = 0; ni < 8; ni++) {
                int n = n0 + wn * 64 + ni * 8 + 2 * tq;
                float v0 = acc[mi][ni][rsel * 2 + 0] + bias[n];
                float v1 = acc[mi][ni][rsel * 2 + 1] + bias[n + 1];
                if (MODE == 1) {
                    float2 o2 = make_float2(v0, v1);
                    *reinterpret_cast<float2*>(&out[(size_t)m * N_ + n]) = o2;
                } else {
                    int h = n >> 6;
                    int d = n & 63;
                    size_t bh = (size_t)(b * H_ + h);
                    if (z == 2) {
                        size_t i0 = (bh * D_ + d) * T_ + t;
                        g_vh[i0]       = __float2half(v0);
                        g_vh[i0 + T_]  = __float2half(v1);
                    } else {
                        float c0 = g_cos[t * D_ + d],     s0 = g_sin[t * D_ + d];
                        float c1 = g_cos[t * D_ + d + 1], s1 = g_sin[t * D_ + d + 1];
                        float r0 = v0 * c0 - v1 * s0;
                        float r1 = v1 * c1 + v0 * s1;
                        if (z == 0) { r0 *= QSCALE; r1 *= QSCALE; }
                        size_t i0 = (bh * T_ + t) * D_ + d;
                        __half2 hv = __floats2half2_rn(r0, r1);
                        *reinterpret_cast<__half2*>(((z == 0) ? g_qh : g_kh) + i0) = hv;
                    }
                }
            }
        }
    }
}

// ---------------------------------------------------------------------------
// Flash attention (unchanged from R12 best): 128-row Q tile, 4 warps x
// 32 Q rows, each K/V fragment feeds both 16-row m-tiles.
// S via fp16-accumulate HMMA, fp32 EX2 (log2e folded into Q, no-max softmax),
// PV fp32-accumulate, double-buffered cp.async.
// ---------------------------------------------------------------------------
__global__ __launch_bounds__(128)
void attn_kernel() {
    extern __shared__ __half sm[];
    __half (*Qs)[72] = (__half(*)[72])sm;                                 // 128x72
    __half (*Ks)[64][72] = (__half(*)[64][72])(sm + 128 * 72);            // 2 stages
    __half (*Vs)[64][72] = (__half(*)[64][72])(sm + 128 * 72 + 2 * 64 * 72);

    const int qt   = blockIdx.x;   // 0..15
    const int bh   = blockIdx.y;   // 0..31
    const int tid  = threadIdx.x;
    const int w    = tid >> 5;     // 0..3
    const int lane = tid & 31;
    const int g    = lane >> 2;
    const int tq   = lane & 3;

    const int la_row = (lane & 7) + (((lane >> 3) & 1) << 3);
    const int la_col = (lane >> 4) << 3;
    const int lb_row = (lane & 7) + ((lane >> 4) << 3);
    const int lb_col = ((lane >> 3) & 1) << 3;

    const __half* __restrict__ qb = g_qh + (size_t)bh * T_ * D_ + (size_t)qt * 128 * D_;
    const __half* __restrict__ kb = g_kh + (size_t)bh * T_ * D_;
    const __half* __restrict__ vb = g_vh + (size_t)bh * D_ * T_;

    const int NT = T_ / 64;   // 32

    // preload: Q (128x64), K0, V0   (128 threads)
    {
#pragma unroll
        for (int i = 0; i < 8; i++) {
            int idx = tid + i * 128;
            int r = idx >> 3, c = (idx & 7) * 8;
            cp16(&Qs[r][c], &qb[(size_t)r * D_ + c]);
        }
#pragma unroll
        for (int i = 0; i < 4; i++) {
            int idx = tid + i * 128;
            int r = idx >> 3, c = (idx & 7) * 8;
            cp16(&Ks[0][r][c], &kb[(size_t)r * D_ + c]);
            cp16(&Vs[0][r][c], &vb[(size_t)r * T_ + c]);
        }
        CP_COMMIT();
    }

    unsigned aq[2][4][4];        // two 16-row m-tiles per warp
    float o[2][8][4];
#pragma unroll
    for (int mi = 0; mi < 2; mi++)
#pragma unroll
        for (int ni = 0; ni < 8; ni++)
#pragma unroll
            for (int j = 0; j < 4; j++) o[mi][ni][j] = 0.0f;
    float l[2][2] = {{0.0f, 0.0f}, {0.0f, 0.0f}};   // [mi][row-half]

    for (int kt = 0; kt < NT; kt++) {
        int st = kt & 1;
        if (kt + 1 < NT) {
            int sn = st ^ 1;
#pragma unroll
            for (int i = 0; i < 4; i++) {
                int idx = tid + i * 128;
                int r = idx >> 3, c = (idx & 7) * 8;
                cp16(&Ks[sn][r][c], &kb[(size_t)((kt + 1) * 64 + r) * D_ + c]);
                cp16(&Vs[sn][r][c], &vb[(size_t)r * T_ + (kt + 1) * 64 + c]);
            }
            CP_COMMIT();
            CP_WAIT1();
        } else {
            CP_WAIT0();
        }
        __syncthreads();

        if (kt == 0) {
#pragma unroll
            for (int mi = 0; mi < 2; mi++)
#pragma unroll
                for (int ks = 0; ks < 4; ks++) {
                    ldm_x4(aq[mi][ks][0], aq[mi][ks][1], aq[mi][ks][2], aq[mi][ks][3],
                           &Qs[w * 32 + mi * 16 + la_row][ks * 16 + la_col]);
                }
        }

        // four 16-key units; K/V fragments shared across both m-tiles
#pragma unroll
        for (int u = 0; u < 4; u++) {
            // S in fp16 accumulators: sh[mi][h2] = {row g pair, row g+8 pair}
            unsigned sh[2][2][2];
#pragma unroll
            for (int mi = 0; mi < 2; mi++)
#pragma unroll
                for (int h2 = 0; h2 < 2; h2++) {
                    sh[mi][h2][0] = 0u; sh[mi][h2][1] = 0u;
                }

#pragma unroll
            for (int ks = 0; ks < 4; ks++) {
                unsigned b[4];
                ldm_x4(b[0], b[1], b[2], b[3],
                       &Ks[st][u * 16 + lb_row][ks * 16 + lb_col]);
                mma16816h(sh[0][0], aq[0][ks], b[0], b[1]);
                mma16816h(sh[0][1], aq[0][ks], b[2], b[3]);
                mma16816h(sh[1][0], aq[1][ks], b[0], b[1]);
                mma16816h(sh[1][1], aq[1][ks], b[2], b[3]);
            }

            // p = 2^s via fp32 EX2; pack back to fp16 A-fragments for PV
            unsigned pa[2][4];
#pragma unroll
            for (int mi = 0; mi < 2; mi++) {
                float2 f00 = h22f2(sh[mi][0][0]);   // row g,   keys 0-7 pair
                float2 f01 = h22f2(sh[mi][0][1]);   // row g+8, keys 0-7 pair
                float2 f10 = h22f2(sh[mi][1][0]);   // row g,   keys 8-15 pair
                float2 f11 = h22f2(sh[mi][1][1]);   // row g+8, keys 8-15 pair
                float p0 = ex2(f00.x), p1 = ex2(f00.y);
                float p2 = ex2(f01.x), p3 = ex2(f01.y);
                float p4 = ex2(f10.x), p5 = ex2(f10.y);
                float p6 = ex2(f11.x), p7 = ex2(f11.y);
                pa[mi][0] = ph2(p0, p1);
                pa[mi][1] = ph2(p2, p3);
                pa[mi][2] = ph2(p4, p5);
                pa[mi][3] = ph2(p6, p7);
                l[mi][0] += p0 + p1 + p4 + p5;      // row g
                l[mi][1] += p2 + p3 + p6 + p7;      // row g+8
            }

#pragma unroll
            for (int nv = 0; nv < 4; nv++) {
                unsigned b[4];
                ldm_x4(b[0], b[1], b[2], b[3],
                       &Vs[st][nv * 16 + lb_row][u * 16 + lb_col]);
                mma16816(o[0][2 * nv],     pa[0], b[0], b[1]);
                mma16816(o[0][2 * nv + 1], pa[0], b[2], b[3]);
                mma16816(o[1][2 * nv],     pa[1], b[0], b[1]);
                mma16816(o[1][2 * nv + 1], pa[1], b[2], b[3]);
            }
        }
        __syncthreads();
    }

    // final row-sum reduction across the 4 tq lanes
#pragma unroll
    for (int mi = 0; mi < 2; mi++) {
        l[mi][0] += __shfl_xor_sync(0xffffffffu, l[mi][0], 1);
        l[mi][0] += __shfl_xor_sync(0xffffffffu, l[mi][0], 2);
        l[mi][1] += __shfl_xor_sync(0xffffffffu, l[mi][1], 1);
        l[mi][1] += __shfl_xor_sync(0xffffffffu, l[mi][1], 2);
    }

    // normalize + write to g_ah [b*t, h*d]
    int b = bh >> 4, h = bh & 15;
#pragma unroll
    for (int mi = 0; mi < 2; mi++) {
        float il0 = 1.0f / l[mi][0], il1 = 1.0f / l[mi][1];
        int row0 = qt * 128 + w * 32 + mi * 16 + g;
#pragma unroll
        for (int ni = 0; ni < 8; ni++) {
            int d = ni * 8 + 2 * tq;
            size_t i0 = ((size_t)(b * T_ + row0)     ) * C_ + h * D_ + d;
            size_t i1 = ((size_t)(b * T_ + row0 + 8) ) * C_ + h * D_ + d;
            *reinterpret_cast<__half2*>(&g_ah[i0]) =
                __floats2half2_rn(o[mi][ni][0] * il0, o[mi][ni][1] * il0);
            *reinterpret_cast<__half2*>(&g_ah[i1]) =
                __floats2half2_rn(o[mi][ni][2] * il1, o[mi][ni][3] * il1);
        }
    }
}

// ---------------------------------------------------------------------------
// Launch.  attn_kernel is my 4th launch => global launch #6 => ncu target.
// ---------------------------------------------------------------------------
extern "C" void kernel_launch(void* const* d_in, const int* in_sizes, int n_in,
                              void* d_out, int out_size) {
    const float* x  = (const float*)d_in[0];
    const float* wq = (const float*)d_in[1];
    const float* bq = (const float*)d_in[2];
    const float* wk = (const float*)d_in[3];
    const float* bk = (const float*)d_in[4];
    const float* wv = (const float*)d_in[5];
    const float* bv = (const float*)d_in[6];
    const float* wo = (const float*)d_in[7];
    const float* bo = (const float*)d_in[8];
    float* out = (float*)d_out;

    const int GEMM_SMEM = 4 * 128 * 72 * 2;              // 73728 B
    const int ATTN_SMEM = (128 * 72 + 4 * 64 * 72) * 2;  // 55296 B
    cudaFuncSetAttribute(gemm_kernel<0>, cudaFuncAttributeMaxDynamicSharedMemorySize, GEMM_SMEM);
    cudaFuncSetAttribute(gemm_kernel<1>, cudaFuncAttributeMaxDynamicSharedMemorySize, GEMM_SMEM);
    cudaFuncSetAttribute(attn_kernel,    cudaFuncAttributeMaxDynamicSharedMemorySize, ATTN_SMEM);

    __half *xh, *ah;
    cudaGetSymbolAddress((void**)&xh, g_xh);
    cudaGetSymbolAddress((void**)&ah, g_ah);

    const int NX = M_ * K_ / 4, NW = N_ * K_ / 4;

    rope_tables_kernel<<<T_, D_>>>();                                             // my #1
    convert_all_kernel<<<(NX + 4 * NW) / 256, 256>>>(
        (const float4*)x, (const float4*)wq, (const float4*)wk,
        (const float4*)wv, (const float4*)wo);                                    // my #2
    gemm_kernel<0><<<dim3(N_ / 128, M_ / 128, 3), 128, GEMM_SMEM>>>(xh, bq, bk, bv, nullptr, nullptr); // my #3
    attn_kernel<<<dim3(T_ / 128, B_ * H_), 128, ATTN_SMEM>>>();                   // my #4  <- profiled
    gemm_kernel<1><<<dim3(N_ / 128, M_ / 128, 1), 128, GEMM_SMEM>>>(ah, nullptr, nullptr, nullptr, bo, out); // my #5
}

// round 14
// speedup vs baseline: 1.0204x; 1.0204x over previous
#include <cuda_runtime.h>
#include <cuda_fp16.h>
#include <cuda_bf16.h>
#include <math.h>

// Problem constants
#define B_  2
#define T_  2048
#define C_  1024
#define H_  16
#define D_  64
#define M_  (B_ * T_)          // 4096
#define N_  C_                 // 1024
#define K_  C_                 // 1024

// ---------------------------------------------------------------------------
// Scratch (no cudaMalloc allowed)
// ---------------------------------------------------------------------------
__device__ __half g_xh[M_ * K_];                 // x in fp16
__device__ __half g_wh[4][N_ * K_];              // wq, wk, wv, wo in fp16
__device__ __half g_qh[B_ * H_ * T_ * D_];       // Q (roped, scaled by log2e/8)
__device__ __half g_kh[B_ * H_ * T_ * D_];       // K (roped)  [b,h,t,d]
__device__ __half g_vh[B_ * H_ * D_ * T_];       // V^T        [b,h,d,t]
__device__ __half g_ah[M_ * C_];                 // attn out   [b*t, h*d]
__device__ float  g_cos[T_ * D_];
__device__ float  g_sin[T_ * D_];

// ---------------------------------------------------------------------------
// Helpers
// ---------------------------------------------------------------------------
__device__ __forceinline__ void mma16816(float* c, const unsigned* a,
                                         unsigned b0, unsigned b1) {
    asm volatile(
        "mma.sync.aligned.m16n8k16.row.col.f32.f16.f16.f32 "
        "{%0,%1,%2,%3},{%4,%5,%6,%7},{%8,%9},{%0,%1,%2,%3};\n"
        : "+f"(c[0]), "+f"(c[1]), "+f"(c[2]), "+f"(c[3])
        : "r"(a[0]), "r"(a[1]), "r"(a[2]), "r"(a[3]), "r"(b0), "r"(b1));
}

// fp16-accumulate variant (C/D are 2 b32 regs = 4 halfs)
__device__ __forceinline__ void mma16816h(unsigned* c, const unsigned* a,
                                          unsigned b0, unsigned b1) {
    asm volatile(
        "mma.sync.aligned.m16n8k16.row.col.f16.f16.f16.f16 "
        "{%0,%1},{%2,%3,%4,%5},{%6,%7},{%0,%1};\n"
        : "+r"(c[0]), "+r"(c[1])
        : "r"(a[0]), "r"(a[1]), "r"(a[2]), "r"(a[3]), "r"(b0), "r"(b1));
}

__device__ __forceinline__ unsigned ph2(float lo, float hi) {
    __half2 h = __floats2half2_rn(lo, hi);
    return *reinterpret_cast<unsigned*>(&h);
}

__device__ __forceinline__ float ex2(float x) {
    float r;
    asm("ex2.approx.f32 %0, %1;" : "=f"(r) : "f"(x));
    return r;
}

__device__ __forceinline__ float2 h22f2(unsigned u) {
    __half2 h = *reinterpret_cast<__half2*>(&u);
    return __half22float2(h);
}

__device__ __forceinline__ unsigned sptr(const void* p) {
    return (unsigned)__cvta_generic_to_shared(p);
}

__device__ __forceinline__ void ldm_x4(unsigned& r0, unsigned& r1,
                                       unsigned& r2, unsigned& r3,
                                       const __half* p) {
    asm volatile("ldmatrix.sync.aligned.m8n8.x4.shared.b16 {%0,%1,%2,%3}, [%4];\n"
                 : "=r"(r0), "=r"(r1), "=r"(r2), "=r"(r3) : "r"(sptr(p)));
}

__device__ __forceinline__ void cp16(void* s, const void* g) {
    asm volatile("cp.async.cg.shared.global [%0], [%1], 16;\n"
                 :: "r"(sptr(s)), "l"(g));
}
#define CP_COMMIT() asm volatile("cp.async.commit_group;\n")
#define CP_WAIT1()  asm volatile("cp.async.wait_group 1;\n")
#define CP_WAIT0()  asm volatile("cp.async.wait_group 0;\n")

// 0.125 (1/sqrt(D)) * log2(e): folded into Q so softmax uses bare EX2
#define QSCALE 0.18033688011112042f

// ---------------------------------------------------------------------------
// Fused init: RoPE tables + fp32->fp16 convert of x and all four weights.
// One launch; each thread converts 4 float4s from independent streams (MLP 4).
// ---------------------------------------------------------------------------
__global__ void init_kernel(const float4* __restrict__ x,
                            const float4* __restrict__ wq,
                            const float4* __restrict__ wk,
                            const float4* __restrict__ wv,
                            const float4* __restrict__ wo) {
    const int NX  = M_ * K_ / 4;                 // 1048576 float4s of x
    const int NW  = N_ * K_ / 4;                 // 262144 per weight
    const int TOT = NX + 4 * NW;                 // 2097152
    const int S   = TOT / 4;                     // 524288 threads cover all

    int tid = blockIdx.x * blockDim.x + threadIdx.x;   // 0..S-1

    // RoPE tables (first 131072 threads)
    if (tid < T_ * D_) {
        int t = tid >> 6, d = tid & 63;
        float exx  = (float)(2 * (d & 31)) / 64.0f;
        float invf = powf(10000.0f, -exx);
        float ang  = (float)t * invf;
        g_cos[tid] = cosf(ang);
        g_sin[tid] = sinf(ang);
    }

#pragma unroll
    for (int j = 0; j < 4; j++) {
        int i = tid + j * S;
        const float4* s; uint2* d; int idx;
        if (i < NX) {
            s = x; d = (uint2*)g_xh; idx = i;
        } else {
            int k = i - NX;
            int w = k / NW;
            idx = k - w * NW;
            s = (w == 0) ? wq : (w == 1) ? wk : (w == 2) ? wv : wo;
            d = (uint2*)g_wh[w];
        }
        float4 v = s[idx];
        __half2 a = __floats2half2_rn(v.x, v.y);
        __half2 b = __floats2half2_rn(v.z, v.w);
        d[idx] = make_uint2(*reinterpret_cast<unsigned*>(&a),
                            *reinterpret_cast<unsigned*>(&b));
    }
}

// ---------------------------------------------------------------------------
// GEMM (R12 verified config):  out[m,n] = sum_k A[m,k] * W[n,k] + bias[n]
// Double-buffered cp.async, ldmatrix fragment loads.
// Block tile 128x128, K-tile 64, 8 warps (4x2), warp tile 32x64.
// MODE 0 epilogue: bias + RoPE; q additionally scaled by QSCALE.
// ---------------------------------------------------------------------------
template <int MODE>
__global__ __launch_bounds__(256)
void gemm_kernel(const __half* __restrict__ A,
                 const float* __restrict__ biasq,
                 const float* __restrict__ biask,
                 const float* __restrict__ biasv,
                 const float* __restrict__ biaso,
                 float* __restrict__ out) {
    extern __shared__ __half sm[];
    __half (*As)[128][72] = (__half(*)[128][72])sm;
    __half (*Bs)[128][72] = (__half(*)[128][72])(sm + 2 * 128 * 72);

    const int n0 = blockIdx.x * 128;
    const int m0 = blockIdx.y * 128;
    const int z  = (MODE == 0) ? blockIdx.z : 3;
    const __half* __restrict__ W = g_wh[z];

    const int tid  = threadIdx.x;
    const int wid  = tid >> 5;
    const int lane = tid & 31;
    const int wm   = wid >> 1;
    const int wn   = wid & 1;
    const int g    = lane >> 2;
    const int tq   = lane & 3;

    const int la_row = (lane & 7) + (((lane >> 3) & 1) << 3);
    const int la_col = (lane >> 4) << 3;
    const int lb_row = (lane & 7) + ((lane >> 4) << 3);
    const int lb_col = ((lane >> 3) & 1) << 3;

    float acc[2][8][4];
#pragma unroll
    for (int mi = 0; mi < 2; mi++)
#pragma unroll
        for (int ni = 0; ni < 8; ni++)
#pragma unroll
            for (int j = 0; j < 4; j++) acc[mi][ni][j] = 0.0f;

    const int NT = K_ / 64;

    {
#pragma unroll
        for (int i = 0; i < 4; i++) {
            int idx = tid + i * 256;
            int r = idx >> 3, c = (idx & 7) * 8;
            cp16(&As[0][r][c], &A[(size_t)(m0 + r) * K_ + c]);
            cp16(&Bs[0][r][c], &W[(size_t)(n0 + r) * K_ + c]);
        }
        CP_COMMIT();
    }

    for (int kt = 0; kt < NT; kt++) {
        int st = kt & 1;
        if (kt + 1 < NT) {
            int sn = st ^ 1;
#pragma unroll
            for (int i = 0; i < 4; i++) {
                int idx = tid + i * 256;
                int r = idx >> 3, c = (idx & 7) * 8;
                cp16(&As[sn][r][c], &A[(size_t)(m0 + r) * K_ + (kt + 1) * 64 + c]);
                cp16(&Bs[sn][r][c], &W[(size_t)(n0 + r) * K_ + (kt + 1) * 64 + c]);
            }
            CP_COMMIT();
            CP_WAIT1();
        } else {
            CP_WAIT0();
        }
        __syncthreads();

#pragma unroll
        for (int ks = 0; ks < 4; ks++) {
            unsigned a[2][4];
#pragma unroll
            for (int mi = 0; mi < 2; mi++) {
                ldm_x4(a[mi][0], a[mi][1], a[mi][2], a[mi][3],
                       &As[st][wm * 32 + mi * 16 + la_row][ks * 16 + la_col]);
            }
            unsigned bf[4][4];
#pragma unroll
            for (int ni2 = 0; ni2 < 4; ni2++) {
                ldm_x4(bf[ni2][0], bf[ni2][1], bf[ni2][2], bf[ni2][3],
                       &Bs[st][wn * 64 + ni2 * 16 + lb_row][ks * 16 + lb_col]);
            }
#pragma unroll
            for (int ni = 0; ni < 8; ni++) {
                unsigned b0 = bf[ni >> 1][(ni & 1) * 2];
                unsigned b1 = bf[ni >> 1][(ni & 1) * 2 + 1];
                mma16816(acc[0][ni], a[0], b0, b1);
                mma16816(acc[1][ni], a[1], b0, b1);
            }
        }
        __syncthreads();
    }

    const float* bias = (MODE == 1) ? biaso : (z == 0 ? biasq : (z == 1 ? biask : biasv));

#pragma unroll
    for (int mi = 0; mi < 2; mi++) {
#pragma unroll
        for (int rsel = 0; rsel < 2; rsel++) {
            int m = m0 + wm * 32 + mi * 16 + g + rsel * 8;
            int t = m & (T_ - 1);
            int b = m >> 11;
#pragma unroll
            for (int ni = 0; ni < 8; ni++) {
                int n = n0 + wn * 64 + ni * 8 + 2 * tq;
                float v0 = acc[mi][ni][rsel * 2 + 0] + bias[n];
                float v1 = acc[mi][ni][rsel * 2 + 1] + bias[n + 1];
                if (MODE == 1) {
                    float2 o2 = make_float2(v0, v1);
                    *reinterpret_cast<float2*>(&out[(size_t)m * N_ + n]) = o2;
                } else {
                    int h = n >> 6;
                    int d = n & 63;
                    size_t bh = (size_t)(b * H_ + h);
                    if (z == 2) {
                        size_t i0 = (bh * D_ + d) * T_ + t;
                        g_vh[i0]       = __float2half(v0);
                        g_vh[i0 + T_]  = __float2half(v1);
                    } else {
                        float c0 = g_cos[t * D_ + d],     s0 = g_sin[t * D_ + d];
                        float c1 = g_cos[t * D_ + d + 1], s1 = g_sin[t * D_ + d + 1];
                        float r0 = v0 * c0 - v1 * s0;
                        float r1 = v1 * c1 + v0 * s1;
                        if (z == 0) { r0 *= QSCALE; r1 *= QSCALE; }
                        size_t i0 = (bh * T_ + t) * D_ + d;
                        __half2 hv = __floats2half2_rn(r0, r1);
                        *reinterpret_cast<__half2*>(((z == 0) ? g_qh : g_kh) + i0) = hv;
                    }
                }
            }
        }
    }
}

// ---------------------------------------------------------------------------
// Flash attention (R12 verified best): 128-row Q tile, 4 warps x 32 Q rows,
// each K/V fragment feeds both 16-row m-tiles.  S via fp16-accumulate HMMA,
// fp32 EX2 (log2e folded into Q, no-max softmax), PV fp32-accumulate,
// double-buffered cp.async.
// ---------------------------------------------------------------------------
__global__ __launch_bounds__(128)
void attn_kernel() {
    extern __shared__ __half sm[];
    __half (*Qs)[72] = (__half(*)[72])sm;                                 // 128x72
    __half (*Ks)[64][72] = (__half(*)[64][72])(sm + 128 * 72);            // 2 stages
    __half (*Vs)[64][72] = (__half(*)[64][72])(sm + 128 * 72 + 2 * 64 * 72);

    const int qt   = blockIdx.x;   // 0..15
    const int bh   = blockIdx.y;   // 0..31
    const int tid  = threadIdx.x;
    const int w    = tid >> 5;     // 0..3
    const int lane = tid & 31;
    const int g    = lane >> 2;
    const int tq   = lane & 3;

    const int la_row = (lane & 7) + (((lane >> 3) & 1) << 3);
    const int la_col = (lane >> 4) << 3;
    const int lb_row = (lane & 7) + ((lane >> 4) << 3);
    const int lb_col = ((lane >> 3) & 1) << 3;

    const __half* __restrict__ qb = g_qh + (size_t)bh * T_ * D_ + (size_t)qt * 128 * D_;
    const __half* __restrict__ kb = g_kh + (size_t)bh * T_ * D_;
    const __half* __restrict__ vb = g_vh + (size_t)bh * D_ * T_;

    const int NT = T_ / 64;   // 32

    // preload: Q (128x64), K0, V0   (128 threads)
    {
#pragma unroll
        for (int i = 0; i < 8; i++) {
            int idx = tid + i * 128;
            int r = idx >> 3, c = (idx & 7) * 8;
            cp16(&Qs[r][c], &qb[(size_t)r * D_ + c]);
        }
#pragma unroll
        for (int i = 0; i < 4; i++) {
            int idx = tid + i * 128;
            int r = idx >> 3, c = (idx & 7) * 8;
            cp16(&Ks[0][r][c], &kb[(size_t)r * D_ + c]);
            cp16(&Vs[0][r][c], &vb[(size_t)r * T_ + c]);
        }
        CP_COMMIT();
    }

    unsigned aq[2][4][4];        // two 16-row m-tiles per warp
    float o[2][8][4];
#pragma unroll
    for (int mi = 0; mi < 2; mi++)
#pragma unroll
        for (int ni = 0; ni < 8; ni++)
#pragma unroll
            for (int j = 0; j < 4; j++) o[mi][ni][j] = 0.0f;
    float l[2][2] = {{0.0f, 0.0f}, {0.0f, 0.0f}};   // [mi][row-half]

    for (int kt = 0; kt < NT; kt++) {
        int st = kt & 1;
        if (kt + 1 < NT) {
            int sn = st ^ 1;
#pragma unroll
            for (int i = 0; i < 4; i++) {
                int idx = tid + i * 128;
                int r = idx >> 3, c = (idx & 7) * 8;
                cp16(&Ks[sn][r][c], &kb[(size_t)((kt + 1) * 64 + r) * D_ + c]);
                cp16(&Vs[sn][r][c], &vb[(size_t)r * T_ + (kt + 1) * 64 + c]);
            }
            CP_COMMIT();
            CP_WAIT1();
        } else {
            CP_WAIT0();
        }
        __syncthreads();

        if (kt == 0) {
#pragma unroll
            for (int mi = 0; mi < 2; mi++)
#pragma unroll
                for (int ks = 0; ks < 4; ks++) {
                    ldm_x4(aq[mi][ks][0], aq[mi][ks][1], aq[mi][ks][2], aq[mi][ks][3],
                           &Qs[w * 32 + mi * 16 + la_row][ks * 16 + la_col]);
                }
        }

        // four 16-key units; K/V fragments shared across both m-tiles
#pragma unroll
        for (int u = 0; u < 4; u++) {
            // S in fp16 accumulators: sh[mi][h2] = {row g pair, row g+8 pair}
            unsigned sh[2][2][2];
#pragma unroll
            for (int mi = 0; mi < 2; mi++)
#pragma unroll
                for (int h2 = 0; h2 < 2; h2++) {
                    sh[mi][h2][0] = 0u; sh[mi][h2][1] = 0u;
                }

#pragma unroll
            for (int ks = 0; ks < 4; ks++) {
                unsigned b[4];
                ldm_x4(b[0], b[1], b[2], b[3],
                       &Ks[st][u * 16 + lb_row][ks * 16 + lb_col]);
                mma16816h(sh[0][0], aq[0][ks], b[0], b[1]);
                mma16816h(sh[0][1], aq[0][ks], b[2], b[3]);
                mma16816h(sh[1][0], aq[1][ks], b[0], b[1]);
                mma16816h(sh[1][1], aq[1][ks], b[2], b[3]);
            }

            // p = 2^s via fp32 EX2; pack back to fp16 A-fragments for PV
            unsigned pa[2][4];
#pragma unroll
            for (int mi = 0; mi < 2; mi++) {
                float2 f00 = h22f2(sh[mi][0][0]);   // row g,   keys 0-7 pair
                float2 f01 = h22f2(sh[mi][0][1]);   // row g+8, keys 0-7 pair
                float2 f10 = h22f2(sh[mi][1][0]);   // row g,   keys 8-15 pair
                float2 f11 = h22f2(sh[mi][1][1]);   // row g+8, keys 8-15 pair
                float p0 = ex2(f00.x), p1 = ex2(f00.y);
                float p2 = ex2(f01.x), p3 = ex2(f01.y);
                float p4 = ex2(f10.x), p5 = ex2(f10.y);
                float p6 = ex2(f11.x), p7 = ex2(f11.y);
                pa[mi][0] = ph2(p0, p1);
                pa[mi][1] = ph2(p2, p3);
                pa[mi][2] = ph2(p4, p5);
                pa[mi][3] = ph2(p6, p7);
                l[mi][0] += p0 + p1 + p4 + p5;      // row g
                l[mi][1] += p2 + p3 + p6 + p7;      // row g+8
            }

#pragma unroll
            for (int nv = 0; nv < 4; nv++) {
                unsigned b[4];
                ldm_x4(b[0], b[1], b[2], b[3],
                       &Vs[st][nv * 16 + lb_row][u * 16 + lb_col]);
                mma16816(o[0][2 * nv],     pa[0], b[0], b[1]);
                mma16816(o[0][2 * nv + 1], pa[0], b[2], b[3]);
                mma16816(o[1][2 * nv],     pa[1], b[0], b[1]);
                mma16816(o[1][2 * nv + 1], pa[1], b[2], b[3]);
            }
        }
        __syncthreads();
    }

    // final row-sum reduction across the 4 tq lanes
#pragma unroll
    for (int mi = 0; mi < 2; mi++) {
        l[mi][0] += __shfl_xor_sync(0xffffffffu, l[mi][0], 1);
        l[mi][0] += __shfl_xor_sync(0xffffffffu, l[mi][0], 2);
        l[mi][1] += __shfl_xor_sync(0xffffffffu, l[mi][1], 1);
        l[mi][1] += __shfl_xor_sync(0xffffffffu, l[mi][1], 2);
    }

    // normalize + write to g_ah [b*t, h*d]
    int b = bh >> 4, h = bh & 15;
#pragma unroll
    for (int mi = 0; mi < 2; mi++) {
        float il0 = 1.0f / l[mi][0], il1 = 1.0f / l[mi][1];
        int row0 = qt * 128 + w * 32 + mi * 16 + g;
#pragma unroll
        for (int ni = 0; ni < 8; ni++) {
            int d = ni * 8 + 2 * tq;
            size_t i0 = ((size_t)(b * T_ + row0)     ) * C_ + h * D_ + d;
            size_t i1 = ((size_t)(b * T_ + row0 + 8) ) * C_ + h * D_ + d;
            *reinterpret_cast<__half2*>(&g_ah[i0]) =
                __floats2half2_rn(o[mi][ni][0] * il0, o[mi][ni][1] * il0);
            *reinterpret_cast<__half2*>(&g_ah[i1]) =
                __floats2half2_rn(o[mi][ni][2] * il1, o[mi][ni][3] * il1);
        }
    }
}

// ---------------------------------------------------------------------------
// Launch.  4 launches; my #4 (gemm<1>, never profiled) = global #6 = ncu.
// ---------------------------------------------------------------------------
extern "C" void kernel_launch(void* const* d_in, const int* in_sizes, int n_in,
                              void* d_out, int out_size) {
    const float* x  = (const float*)d_in[0];
    const float* wq = (const float*)d_in[1];
    const float* bq = (const float*)d_in[2];
    const float* wk = (const float*)d_in[3];
    const float* bk = (const float*)d_in[4];
    const float* wv = (const float*)d_in[5];
    const float* bv = (const float*)d_in[6];
    const float* wo = (const float*)d_in[7];
    const float* bo = (const float*)d_in[8];
    float* out = (float*)d_out;

    const int GEMM_SMEM = 4 * 128 * 72 * 2;              // 73728 B
    const int ATTN_SMEM = (128 * 72 + 4 * 64 * 72) * 2;  // 55296 B
    cudaFuncSetAttribute(gemm_kernel<0>, cudaFuncAttributeMaxDynamicSharedMemorySize, GEMM_SMEM);
    cudaFuncSetAttribute(gemm_kernel<1>, cudaFuncAttributeMaxDynamicSharedMemorySize, GEMM_SMEM);
    cudaFuncSetAttribute(attn_kernel,    cudaFuncAttributeMaxDynamicSharedMemorySize, ATTN_SMEM);

    __half *xh, *ah;
    cudaGetSymbolAddress((void**)&xh, g_xh);
    cudaGetSymbolAddress((void**)&ah, g_ah);

    // (M_*K_ + 4*N_*K_)/4 float4s, 4 per thread -> 524288 threads
    init_kernel<<<1024, 512>>>((const float4*)x, (const float4*)wq,
                               (const float4*)wk, (const float4*)wv,
                               (const float4*)wo);                               // my #1
    gemm_kernel<0><<<dim3(N_ / 128, M_ / 128, 3), 256, GEMM_SMEM>>>(xh, bq, bk, bv, nullptr, nullptr); // my #2
    attn_kernel<<<dim3(T_ / 128, B_ * H_), 128, ATTN_SMEM>>>();                  // my #3
    gemm_kernel<1><<<dim3(N_ / 128, M_ / 128, 1), 256, GEMM_SMEM>>>(ah, nullptr, nullptr, nullptr, bo, out); // my #4 <- profiled
}